// round 8
// baseline (speedup 1.0000x reference)
#include <cuda_runtime.h>
#include <cuda_fp16.h>
#include <cstdint>

#define KCODES 1024
#define CDIM 64
#define NPIX 131072
#define QELEMS 8388608
#define TH2 0.045f      // gap threshold on score/2
#define BIGF 3.4e38f
#define NCTA (NPIX / 128)

// g_B rows (80 halves): [-fp16(e) x64 | h(en/2) | h(en/2 - h(en/2)) | 0 x14]
__device__ __align__(16) __half g_B[KCODES * 80];
__device__ float g_enorm[KCODES];
__device__ float g_loss;
__device__ int g_done;

// ---- smem (bytes). AROWB=176 (88 halves): conflict-free ldmatrix stride ----
#define AROWB 176
#define SM_SA 0                  // half [128 rows][88]  (22528)
#define SM_SB0 22528             // B tile buf0 (22528)
#define SM_SB1 45056             // B tile buf1 (22528)
#define SM_RB1 67584             // float [4][128]
#define SM_RB2 69632
#define SM_RI 71680              // int [4][128] (group base)
#define SM_RIDX 73728            // int [128]
#define SM_GB 74240              // int [128]
#define SM_FLIST 74752
#define SM_FCNT 75264
#define SM_WSUM 75268            // float[16]
#define SM_FS 75332              // float[16]
#define SM_FI 75396              // int[16]
#define SM_TOTAL 75520
// epilogue: sx f32 [128][68] @0 (34816) overlaps sA+sB0 (dead by then)

__device__ __forceinline__ uint32_t smem_u32(const void* p) {
    return (uint32_t)__cvta_generic_to_shared(p);
}
#define LDSM4(r0, r1, r2, r3, a)                                                  \
    asm volatile("ldmatrix.sync.aligned.m8n8.x4.shared.b16 {%0,%1,%2,%3}, [%4];"  \
                 : "=r"(r0), "=r"(r1), "=r"(r2), "=r"(r3) : "r"(a))
#define MMA16816(d, a, b)                                                         \
    asm volatile("mma.sync.aligned.m16n8k16.row.col.f32.f16.f16.f32 "             \
                 "{%0,%1,%2,%3}, {%4,%5,%6,%7}, {%8,%9}, {%0,%1,%2,%3};"          \
                 : "+f"((d)[0]), "+f"((d)[1]), "+f"((d)[2]), "+f"((d)[3])         \
                 : "r"((a)[0]), "r"((a)[1]), "r"((a)[2]), "r"((a)[3]),            \
                   "r"((b)[0]), "r"((b)[1]))
#define CPASYNC16(dst, src)                                                       \
    asm volatile("cp.async.cg.shared.global [%0], [%1], 16;" :: "r"(dst), "l"(src) : "memory")

// ---------------- prep: B rows with enorm dims, zero loss/counter ----------------
__global__ void vq_bsplit(const float* __restrict__ emb) {
    int k = blockIdx.x * 128 + threadIdx.x;
    if (k == 0) { g_loss = 0.0f; g_done = 0; }
    if (k < KCODES) {
        float s = 0.0f;
        __half* br = g_B + k * 80;
#pragma unroll 8
        for (int c = 0; c < CDIM; c += 2) {
            float v0 = emb[k * CDIM + c], v1 = emb[k * CDIM + c + 1];
            s += v0 * v0 + v1 * v1;
            *reinterpret_cast<__half2*>(br + c) = __floats2half2_rn(-v0, -v1);
        }
        g_enorm[k] = s;
        float en2 = 0.5f * s;
        __half h = __float2half_rn(en2);
        br[64] = h;
        br[65] = __float2half_rn(en2 - __half2float(h));
#pragma unroll
        for (int c = 66; c < 80; c++) br[c] = __ushort_as_half((unsigned short)0);
    }
}

// ---------------- fused main ----------------
extern __shared__ char sm_raw[];

__global__ void __launch_bounds__(512, 2) vq_main(const float* __restrict__ x,
                                                  const float* __restrict__ emb,
                                                  float* __restrict__ out) {
    char* sm = sm_raw;
    __half* sA = reinterpret_cast<__half*>(sm + SM_SA);
    int* fcnt = reinterpret_cast<int*>(sm + SM_FCNT);

    const int tid = threadIdx.x, l = tid & 31, w = tid >> 5;
    const int wm = w & 3, wn = w >> 2;      // 4 pixel-blocks x 4 code-blocks
    const int n0 = blockIdx.x * 128;
    const int b = n0 >> 12, rem = n0 & 4095;
    const float* xb = x + (size_t)b * 262144 + rem;
    const uint32_t sBb = smem_u32(sm);

    // prologue: start tile 0 B load (1280 x 16B chunks)
    {
        const char* bsrc = reinterpret_cast<const char*>(g_B);
        for (int i = tid; i < 1280; i += 512) {
            int r = i / 10, q = i - r * 10;
            CPASYNC16(sBb + SM_SB0 + r * AROWB + q * 16, bsrc + r * 160 + q * 16);
        }
        asm volatile("cp.async.commit_group;" ::: "memory");
    }

    if (tid == 0) *fcnt = 0;
    // x -> fp16 transposed into sA (pack 2 channels per STS.32)
    for (int i = tid; i < 4096; i += 512) {
        int c2 = i >> 7, p = i & 127;
        float v0 = xb[(2 * c2) * 4096 + p], v1 = xb[(2 * c2 + 1) * 4096 + p];
        *reinterpret_cast<__half2*>(sA + p * 88 + 2 * c2) = __floats2half2_rn(v0, v1);
    }
    // extra dims: col 64,65 = 1.0 ; 66..79 = 0
    for (int i = tid; i < 2048; i += 512) {
        int p = i >> 4, c = 64 + (i & 15);
        sA[p * 88 + c] = (c < 66) ? __float2half_rn(1.0f) : __ushort_as_half((unsigned short)0);
    }

    // lane-constant ldmatrix addresses
    const int lr = l & 7;
    const uint32_t aB = sBb + SM_SA +
        (uint32_t)(wm * 32 + lr + ((l >> 3) & 1) * 8) * AROWB + ((l >> 4) & 1) * 16;
    const uint32_t bO =
        (uint32_t)(wn * 32 + lr + ((l >> 4) & 1) * 8) * AROWB + ((l >> 3) & 1) * 16;

    float B1[4] = {BIGF, BIGF, BIGF, BIGF};
    float B2[4] = {BIGF, BIGF, BIGF, BIGF};
    int G1[4] = {0, 0, 0, 0};
    const int kwl = wn * 32 + 2 * (l & 3);
    const uint32_t bufOff[2] = {SM_SB0, SM_SB1};

    for (int nt = 0; nt < 8; nt++) {
        if (nt < 7) {
            const char* bsrc = reinterpret_cast<const char*>(g_B) + (size_t)(nt + 1) * 20480;
            uint32_t dstb = sBb + bufOff[(nt + 1) & 1];
            for (int i = tid; i < 1280; i += 512) {
                int r = i / 10, q = i - r * 10;
                CPASYNC16(dstb + r * AROWB + q * 16, bsrc + r * 160 + q * 16);
            }
            asm volatile("cp.async.commit_group;\ncp.async.wait_group 1;" ::: "memory");
        } else {
            asm volatile("cp.async.wait_group 0;" ::: "memory");
        }
        __syncthreads();

        const uint32_t bT = sBb + bufOff[nt & 1] + bO;
#pragma unroll
        for (int half = 0; half < 2; half++) {
            float acc[2][2][4];
#pragma unroll
            for (int mt = 0; mt < 2; mt++)
#pragma unroll
                for (int q = 0; q < 2; q++)
#pragma unroll
                    for (int cc = 0; cc < 4; cc++) acc[mt][q][cc] = 0.0f;

#pragma unroll
            for (int ks = 0; ks < 5; ks++) {
                uint32_t af[2][4];
#pragma unroll
                for (int mt = 0; mt < 2; mt++)
                    LDSM4(af[mt][0], af[mt][1], af[mt][2], af[mt][3],
                          aB + (uint32_t)mt * (16 * AROWB) + (uint32_t)ks * 32);
                uint32_t bf[2][2];
                {
                    uint32_t r0, r1, r2, r3;
                    LDSM4(r0, r1, r2, r3,
                          bT + (uint32_t)half * (16 * AROWB) + (uint32_t)ks * 32);
                    bf[0][0] = r0; bf[0][1] = r1; bf[1][0] = r2; bf[1][1] = r3;
                }
#pragma unroll
                for (int mt = 0; mt < 2; mt++)
#pragma unroll
                    for (int q = 0; q < 2; q++) MMA16816(acc[mt][q], af[mt], bf[q]);
            }

            // group-of-4 fold: group = {base2, base2+1, base2+8, base2+9}
            const int base2 = nt * 128 + half * 16 + kwl;
#pragma unroll
            for (int mt = 0; mt < 2; mt++)
#pragma unroll
                for (int ch = 0; ch < 2; ch++) {
                    int s = mt * 2 + ch;
                    float g = fminf(fminf(acc[mt][0][ch * 2], acc[mt][0][ch * 2 + 1]),
                                    fminf(acc[mt][1][ch * 2], acc[mt][1][ch * 2 + 1]));
                    bool bt = g < B1[s];
                    B2[s] = fminf(B2[s], fmaxf(B1[s], g));
                    B1[s] = fminf(B1[s], g);
                    if (bt) G1[s] = base2;
                }
        }
        __syncthreads();
    }

    // quad reduce over lanes sharing pixel rows (l&3)
#pragma unroll
    for (int off = 1; off <= 2; off <<= 1)
#pragma unroll
        for (int s = 0; s < 4; s++) {
            float ob1 = __shfl_down_sync(0xffffffffu, B1[s], off, 4);
            float ob2 = __shfl_down_sync(0xffffffffu, B2[s], off, 4);
            int og = __shfl_down_sync(0xffffffffu, G1[s], off, 4);
            if (ob1 < B1[s] || (ob1 == B1[s] && og < G1[s])) {
                B2[s] = fminf(ob2, B1[s]); B1[s] = ob1; G1[s] = og;
            } else B2[s] = fminf(B2[s], ob1);
        }
    {
        float* rb1 = reinterpret_cast<float*>(sm + SM_RB1);
        float* rb2 = reinterpret_cast<float*>(sm + SM_RB2);
        int* ri = reinterpret_cast<int*>(sm + SM_RI);
        if ((l & 3) == 0)
#pragma unroll
            for (int s = 0; s < 4; s++) {
                int pr = wm * 32 + (s >> 1) * 16 + (s & 1) * 8 + (l >> 2);
                rb1[wn * 128 + pr] = B1[s];
                rb2[wn * 128 + pr] = B2[s];
                ri[wn * 128 + pr] = G1[s];
            }
    }
    __syncthreads();  // rb ready; sA/sB dead

    // reload exact fp32 x (overlaps sA/sB0)
    float* sx = reinterpret_cast<float*>(sm + SM_SA);
    for (int i = tid; i < 8192; i += 512) {
        int c = i >> 7, p = i & 127;
        sx[p * 68 + c] = xb[c * 4096 + p];
    }

    int* ridx = reinterpret_cast<int*>(sm + SM_RIDX);
    int* gbs = reinterpret_cast<int*>(sm + SM_GB);
    int* flist = reinterpret_cast<int*>(sm + SM_FLIST);
    if (tid < 128) {
        float* rb1 = reinterpret_cast<float*>(sm + SM_RB1);
        float* rb2 = reinterpret_cast<float*>(sm + SM_RB2);
        int* ri = reinterpret_cast<int*>(sm + SM_RI);
        float best = BIGF, second = BIGF; int gb = 0x7fffffff;
#pragma unroll
        for (int j = 0; j < 4; j++) {
            float v1 = rb1[j * 128 + tid], v2 = rb2[j * 128 + tid];
            int gj = ri[j * 128 + tid];
            if (v1 < best || (v1 == best && gj < gb)) {
                second = fminf(v2, best); best = v1; gb = gj;
            } else second = fminf(second, v1);
        }
        gbs[tid] = gb;
        if (second - best < TH2) flist[atomicAdd(fcnt, 1)] = tid;
    }
    __syncthreads();

    // exact in-group resolve: 512 threads = 128 px x 4 candidates
    {
        int px = tid >> 2, cand = tid & 3;
        int code = gbs[px] + ((cand >> 1) << 3) + (cand & 1);
        const float4* er = reinterpret_cast<const float4*>(emb + code * CDIM);
        float dot = 0.0f;
#pragma unroll
        for (int c4 = 0; c4 < 16; c4++) {
            float4 e4 = er[c4];
            float4 x4 = *reinterpret_cast<const float4*>(&sx[px * 68 + c4 * 4]);
            dot += e4.x * x4.x + e4.y * x4.y + e4.z * x4.z + e4.w * x4.w;
        }
        float sc = fmaf(-2.0f, dot, __ldg(&g_enorm[code]));
#pragma unroll
        for (int off = 1; off <= 2; off <<= 1) {
            float os = __shfl_xor_sync(0xffffffffu, sc, off, 4);
            int oc = __shfl_xor_sync(0xffffffffu, code, off, 4);
            if (os < sc || (os == sc && oc < code)) { sc = os; code = oc; }
        }
        if (cand == 0) ridx[px] = code;
    }
    __syncthreads();

    // full exact scan for flagged pixels (2 codes/thread)
    {
        float* fs = reinterpret_cast<float*>(sm + SM_FS);
        int* fi = reinterpret_cast<int*>(sm + SM_FI);
        int nf = *fcnt;
        for (int f = 0; f < nf; f++) {
            int px = flist[f];
            float best = BIGF; int bidx = 0;
#pragma unroll
            for (int kk = 0; kk < 2; kk++) {
                int k = tid * 2 + kk;
                const float4* er = reinterpret_cast<const float4*>(emb + k * CDIM);
                float dot = 0.0f;
#pragma unroll
                for (int c4 = 0; c4 < 16; c4++) {
                    float4 e4 = er[c4];
                    float4 x4 = *reinterpret_cast<const float4*>(&sx[px * 68 + c4 * 4]);
                    dot += e4.x * x4.x + e4.y * x4.y + e4.z * x4.z + e4.w * x4.w;
                }
                float sc = fmaf(-2.0f, dot, __ldg(&g_enorm[k]));
                if (sc < best || (sc == best && k < bidx)) { best = sc; bidx = k; }
            }
#pragma unroll
            for (int off = 16; off > 0; off >>= 1) {
                float os = __shfl_down_sync(0xffffffffu, best, off);
                int oi = __shfl_down_sync(0xffffffffu, bidx, off);
                if (os < best || (os == best && oi < bidx)) { best = os; bidx = oi; }
            }
            if (l == 0) { fs[w] = best; fi[w] = bidx; }
            __syncthreads();
            if (tid == 0) {
                float bb = fs[0]; int bi2 = fi[0];
#pragma unroll
                for (int t = 1; t < 16; t++)
                    if (fs[t] < bb || (fs[t] == bb && fi[t] < bi2)) { bb = fs[t]; bi2 = fi[t]; }
                ridx[px] = bi2;
            }
            __syncthreads();
        }
    }

    if (tid < 128) out[1 + QELEMS + n0 + tid] = (float)ridx[tid];

    // gather quantized, write BCHW, accumulate loss; last CTA finalizes
    {
        float* wsum = reinterpret_cast<float*>(sm + SM_WSUM);
        int px = tid & 127, ch = tid >> 7;  // ch 0..3, 16 channels each
        int bi = ridx[px];
        const float4* erow = reinterpret_cast<const float4*>(emb + bi * CDIM);
        float* qout = out + 1 + (size_t)b * 262144 + rem + px;
        float lsum = 0.0f;
#pragma unroll
        for (int cc = 0; cc < 4; cc++) {
            int c = ch * 16 + cc * 4;
            float4 e4 = erow[c >> 2];
            float4 x4 = *reinterpret_cast<const float4*>(&sx[px * 68 + c]);
            float d0 = e4.x - x4.x, d1 = e4.y - x4.y;
            float d2 = e4.z - x4.z, d3 = e4.w - x4.w;
            lsum += d0 * d0 + d1 * d1 + d2 * d2 + d3 * d3;
            qout[(size_t)(c + 0) * 4096] = e4.x;
            qout[(size_t)(c + 1) * 4096] = e4.y;
            qout[(size_t)(c + 2) * 4096] = e4.z;
            qout[(size_t)(c + 3) * 4096] = e4.w;
        }
#pragma unroll
        for (int o = 16; o > 0; o >>= 1) lsum += __shfl_down_sync(0xffffffffu, lsum, o);
        if (l == 0) wsum[w] = lsum;
        __syncthreads();
        if (tid == 0) {
            float bsum = 0.0f;
#pragma unroll
            for (int ww = 0; ww < 16; ww++) bsum += wsum[ww];
            atomicAdd(&g_loss, bsum);
            __threadfence();
            int old = atomicAdd(&g_done, 1);
            if (old == NCTA - 1) {
                __threadfence();
                float total = atomicAdd(&g_loss, 0.0f);
                out[0] = 0.25f * total * (1.0f / (float)QELEMS);
            }
        }
    }
}

extern "C" void kernel_launch(void* const* d_in, const int* in_sizes, int n_in,
                              void* d_out, int out_size) {
    const float* x = (const float*)d_in[0];
    const float* emb = (const float*)d_in[1];
    if (n_in >= 2 && in_sizes[0] == KCODES * CDIM && in_sizes[1] == NPIX * CDIM) {
        const float* t = x; x = emb; emb = t;
    }
    float* out = (float*)d_out;
    (void)out_size;

    cudaFuncSetAttribute(vq_main, cudaFuncAttributeMaxDynamicSharedMemorySize, SM_TOTAL);

    vq_bsplit<<<8, 128>>>(emb);
    vq_main<<<NCTA, 512, SM_TOTAL>>>(x, emb, out);
}

// round 9
// speedup vs baseline: 1.3174x; 1.3174x over previous
#include <cuda_runtime.h>
#include <cuda_fp16.h>
#include <cstdint>

#define KCODES 1024
#define CDIM 64
#define NPIX 131072
#define QELEMS 8388608
#define TH2 0.002f      // gap threshold on score/2 (err bound < 1e-4 -> 20x margin)
#define BIGF 3.4e38f
#define NCTA (NPIX / 128)

// g_B rows (192 halves): [-fp16(e) x64 | -fp16(e) x64 | -resid(e) x64]
__device__ __align__(16) __half g_B[KCODES * 192];
__device__ float g_enorm[KCODES];
__device__ float g_loss;
__device__ int g_done;

// ---- smem (bytes) ----
#define AROWB 272               // A row stride: 136 halves (conflict-free ldmatrix)
#define BROWB 400               // B row stride: 200 halves (192 used) conflict-free
#define SM_SA 0                 // 128 x 272 = 34816
#define SM_SB0 34816            // 64 x 400 = 25600
#define SM_SB1 60416            // 25600 -> 86016
#define SM_EN 86016             // 4096 -> 90112
#define SM_RB1 90112            // [2][128] f -> 91136
#define SM_RB2 91136            // -> 92160
#define SM_RI 92160             // -> 93184
#define SM_RIDX 93184           // int[128] -> 93696
#define SM_FLIST 93696          // -> 94208
#define SM_FCNT 94208
#define SM_WSUM 94216           // float[8]
#define SM_FS 94248             // float[8]
#define SM_FI 94280             // int[8]
#define SM_TOTAL 94336
// epilogue: sx f32 [128][68] @0 (34816) overlays sA (dead)

__device__ __forceinline__ uint32_t smem_u32(const void* p) {
    return (uint32_t)__cvta_generic_to_shared(p);
}
#define LDSM4(r0, r1, r2, r3, a)                                                  \
    asm volatile("ldmatrix.sync.aligned.m8n8.x4.shared.b16 {%0,%1,%2,%3}, [%4];"  \
                 : "=r"(r0), "=r"(r1), "=r"(r2), "=r"(r3) : "r"(a))
#define MMA16816(d, a, b)                                                         \
    asm volatile("mma.sync.aligned.m16n8k16.row.col.f32.f16.f16.f32 "             \
                 "{%0,%1,%2,%3}, {%4,%5,%6,%7}, {%8,%9}, {%0,%1,%2,%3};"          \
                 : "+f"((d)[0]), "+f"((d)[1]), "+f"((d)[2]), "+f"((d)[3])         \
                 : "r"((a)[0]), "r"((a)[1]), "r"((a)[2]), "r"((a)[3]),            \
                   "r"((b)[0]), "r"((b)[1]))
#define CPASYNC16(dst, src)                                                       \
    asm volatile("cp.async.cg.shared.global [%0], [%1], 16;" :: "r"(dst), "l"(src) : "memory")

// ---------------- prep: B rows (-eh|-eh|-el), enorm, zero accumulators ----------------
__global__ void vq_bsplit(const float* __restrict__ emb) {
    int k = blockIdx.x * 128 + threadIdx.x;
    if (k == 0) { g_loss = 0.0f; g_done = 0; }
    if (k < KCODES) {
        float s = 0.0f;
        __half* br = g_B + k * 192;
#pragma unroll 8
        for (int c = 0; c < CDIM; c += 2) {
            float v0 = emb[k * CDIM + c], v1 = emb[k * CDIM + c + 1];
            s += v0 * v0 + v1 * v1;
            __half h0 = __float2half_rn(v0), h1 = __float2half_rn(v1);
            __half l0 = __float2half_rn(__half2float(h0) - v0);  // -(v - h)
            __half l1 = __float2half_rn(__half2float(h1) - v1);
            __half2 nh = __halves2half2(__hneg(h0), __hneg(h1));
            *reinterpret_cast<__half2*>(br + c) = nh;
            *reinterpret_cast<__half2*>(br + 64 + c) = nh;
            *reinterpret_cast<__half2*>(br + 128 + c) = __halves2half2(l0, l1);
        }
        g_enorm[k] = s;
    }
}

// ---------------- fused main ----------------
extern __shared__ char sm_raw[];

__global__ void __launch_bounds__(256, 2) vq_main(const float* __restrict__ x,
                                                  const float* __restrict__ emb,
                                                  float* __restrict__ out) {
    char* sm = sm_raw;
    __half* sA = reinterpret_cast<__half*>(sm + SM_SA);
    float* en2 = reinterpret_cast<float*>(sm + SM_EN);
    int* fcnt = reinterpret_cast<int*>(sm + SM_FCNT);

    const int tid = threadIdx.x, l = tid & 31, w = tid >> 5;
    const int wm = w & 3, wn = w >> 2;      // 4 m-blocks x 2 n-blocks
    const int n0 = blockIdx.x * 128;
    const int b = n0 >> 12, rem = n0 & 4095;
    const float* xb = x + (size_t)b * 262144 + rem;
    const uint32_t sBb = smem_u32(sm);

    // prologue: tile 0 B load (64 rows x 24 chunks)
    {
        const char* bsrc = reinterpret_cast<const char*>(g_B);
        for (int i = tid; i < 1536; i += 256) {
            int r = i / 24, q = i - r * 24;
            CPASYNC16(sBb + SM_SB0 + r * BROWB + q * 16, bsrc + r * 384 + q * 16);
        }
        asm volatile("cp.async.commit_group;" ::: "memory");
    }

    if (tid == 0) *fcnt = 0;
    for (int i = tid; i < KCODES; i += 256) en2[i] = 0.5f * g_enorm[i];
    // x -> sA: cols [0:64)=xh, [64:128)=xl
    for (int i = tid; i < 4096; i += 256) {
        int c2 = i >> 7, p = i & 127;
        float v0 = xb[(2 * c2) * 4096 + p], v1 = xb[(2 * c2 + 1) * 4096 + p];
        __half h0 = __float2half_rn(v0), h1 = __float2half_rn(v1);
        __half l0 = __float2half_rn(v0 - __half2float(h0));
        __half l1 = __float2half_rn(v1 - __half2float(h1));
        *reinterpret_cast<__half2*>(sA + p * 136 + 2 * c2) = __halves2half2(h0, h1);
        *reinterpret_cast<__half2*>(sA + p * 136 + 64 + 2 * c2) = __halves2half2(l0, l1);
    }

    // lane-constant ldmatrix addresses
    const int lr = l & 7;
    const uint32_t aB = sBb + SM_SA +
        (uint32_t)(wm * 32 + lr + ((l >> 3) & 1) * 8) * AROWB + ((l >> 4) & 1) * 16;
    const uint32_t bO =
        (uint32_t)(wn * 32 + lr + ((l >> 4) & 1) * 8) * BROWB + ((l >> 3) & 1) * 16;

    float B1[4] = {BIGF, BIGF, BIGF, BIGF};
    float B2[4] = {BIGF, BIGF, BIGF, BIGF};
    int I1[4] = {0, 0, 0, 0};
    const int kwl = wn * 32 + 2 * (l & 3);
    const uint32_t bufOff[2] = {SM_SB0, SM_SB1};

    for (int nt = 0; nt < 16; nt++) {
        if (nt > 0) {
            asm volatile("cp.async.wait_group 0;" ::: "memory");
        }
        __syncthreads();  // buf[nt&1] ready; all warps done with buf[(nt+1)&1]
        if (nt < 15) {    // prefetch next tile into the other buffer
            const char* bsrc = reinterpret_cast<const char*>(g_B) + (size_t)(nt + 1) * 24576;
            uint32_t dstb = sBb + bufOff[(nt + 1) & 1];
            for (int i = tid; i < 1536; i += 256) {
                int r = i / 24, q = i - r * 24;
                CPASYNC16(dstb + r * BROWB + q * 16, bsrc + r * 384 + q * 16);
            }
            asm volatile("cp.async.commit_group;" ::: "memory");
        }

        // acc init = enorm/2
        float acc[2][4][4];
        {
            const int base = nt * 64 + kwl;
#pragma unroll
            for (int q = 0; q < 4; q++)
#pragma unroll
                for (int c1 = 0; c1 < 2; c1++) {
                    float e = en2[base + q * 8 + c1];
                    acc[0][q][c1] = e; acc[0][q][c1 + 2] = e;
                    acc[1][q][c1] = e; acc[1][q][c1 + 2] = e;
                }
        }

        const uint32_t bT = sBb + bufOff[nt & 1] + bO;
#pragma unroll
        for (int ks = 0; ks < 12; ks++) {
            const uint32_t colA = (ks < 8) ? (uint32_t)ks * 32 : (uint32_t)(ks - 8) * 32;
            const uint32_t colB = (ks < 8) ? (uint32_t)ks * 32 : 256u + (uint32_t)(ks - 8) * 32;
            uint32_t af[2][4];
#pragma unroll
            for (int mt = 0; mt < 2; mt++)
                LDSM4(af[mt][0], af[mt][1], af[mt][2], af[mt][3],
                      aB + (uint32_t)mt * (16 * AROWB) + colA);
            uint32_t bf[4][2];
#pragma unroll
            for (int q4 = 0; q4 < 2; q4++) {
                uint32_t r0, r1, r2, r3;
                LDSM4(r0, r1, r2, r3, bT + (uint32_t)q4 * (16 * BROWB) + colB);
                bf[q4 * 2][0] = r0; bf[q4 * 2][1] = r1;
                bf[q4 * 2 + 1][0] = r2; bf[q4 * 2 + 1][1] = r3;
            }
#pragma unroll
            for (int mt = 0; mt < 2; mt++)
#pragma unroll
                for (int q = 0; q < 4; q++) MMA16816(acc[mt][q], af[mt], bf[q]);
        }

        // fold (acc == score/2); codes ascend per slot -> strict < keeps lowest idx
        const int kb = nt * 64 + kwl;
#pragma unroll
        for (int mt = 0; mt < 2; mt++)
#pragma unroll
            for (int q = 0; q < 4; q++)
#pragma unroll
                for (int cc = 0; cc < 4; cc++) {
                    int code = kb + q * 8 + (cc & 1);
                    int s = mt * 2 + (cc >> 1);
                    float sc = acc[mt][q][cc];
                    if (sc < B1[s]) { B2[s] = B1[s]; B1[s] = sc; I1[s] = code; }
                    else B2[s] = fminf(B2[s], sc);
                }
    }
    __syncthreads();

    // quad reduce over lanes sharing pixel rows
#pragma unroll
    for (int off = 1; off <= 2; off <<= 1)
#pragma unroll
        for (int s = 0; s < 4; s++) {
            float ob1 = __shfl_down_sync(0xffffffffu, B1[s], off, 4);
            float ob2 = __shfl_down_sync(0xffffffffu, B2[s], off, 4);
            int oi = __shfl_down_sync(0xffffffffu, I1[s], off, 4);
            if (ob1 < B1[s] || (ob1 == B1[s] && oi < I1[s])) {
                B2[s] = fminf(ob2, B1[s]); B1[s] = ob1; I1[s] = oi;
            } else B2[s] = fminf(B2[s], ob1);
        }
    {
        float* rb1 = reinterpret_cast<float*>(sm + SM_RB1);
        float* rb2 = reinterpret_cast<float*>(sm + SM_RB2);
        int* ri = reinterpret_cast<int*>(sm + SM_RI);
        if ((l & 3) == 0)
#pragma unroll
            for (int s = 0; s < 4; s++) {
                int pr = wm * 32 + (s >> 1) * 16 + (s & 1) * 8 + (l >> 2);
                rb1[wn * 128 + pr] = B1[s];
                rb2[wn * 128 + pr] = B2[s];
                ri[wn * 128 + pr] = I1[s];
            }
    }
    __syncthreads();  // rb ready; sA/sB dead

    // reload exact fp32 x (overlays sA)
    float* sx = reinterpret_cast<float*>(sm + SM_SA);
    for (int i = tid; i < 8192; i += 256) {
        int c = i >> 7, p = i & 127;
        sx[p * 68 + c] = xb[c * 4096 + p];
    }

    int* ridx = reinterpret_cast<int*>(sm + SM_RIDX);
    int* flist = reinterpret_cast<int*>(sm + SM_FLIST);
    if (tid < 128) {
        float* rb1 = reinterpret_cast<float*>(sm + SM_RB1);
        float* rb2 = reinterpret_cast<float*>(sm + SM_RB2);
        int* ri = reinterpret_cast<int*>(sm + SM_RI);
        float a1 = rb1[tid], a2 = rb2[tid]; int ai = ri[tid];
        float c1 = rb1[128 + tid], c2 = rb2[128 + tid]; int ci = ri[128 + tid];
        float best, second; int bi;
        if (c1 < a1 || (c1 == a1 && ci < ai)) { best = c1; bi = ci; second = fminf(c2, a1); }
        else { best = a1; bi = ai; second = fminf(a2, c1); }
        ridx[tid] = bi;
        if (second - best < TH2) flist[atomicAdd(fcnt, 1)] = tid;
    }
    __syncthreads();

    // exact fp32 fixup for close calls (rare: TH2 = 2e-3)
    {
        float* fs = reinterpret_cast<float*>(sm + SM_FS);
        int* fi = reinterpret_cast<int*>(sm + SM_FI);
        int nf = *fcnt;
        for (int f = 0; f < nf; f++) {
            int px = flist[f];
            float best = BIGF; int bidx = 0;
#pragma unroll
            for (int kk = 0; kk < 4; kk++) {
                int k = tid * 4 + kk;
                const float4* er = reinterpret_cast<const float4*>(emb + k * CDIM);
                float dot = 0.0f;
#pragma unroll
                for (int c4 = 0; c4 < 16; c4++) {
                    float4 e4 = er[c4];
                    float4 x4 = *reinterpret_cast<const float4*>(&sx[px * 68 + c4 * 4]);
                    dot += e4.x * x4.x + e4.y * x4.y + e4.z * x4.z + e4.w * x4.w;
                }
                float sc = fmaf(-2.0f, dot, __ldg(&g_enorm[k]));
                if (sc < best || (sc == best && k < bidx)) { best = sc; bidx = k; }
            }
#pragma unroll
            for (int off = 16; off > 0; off >>= 1) {
                float os = __shfl_down_sync(0xffffffffu, best, off);
                int oi = __shfl_down_sync(0xffffffffu, bidx, off);
                if (os < best || (os == best && oi < bidx)) { best = os; bidx = oi; }
            }
            if (l == 0) { fs[w] = best; fi[w] = bidx; }
            __syncthreads();
            if (tid == 0) {
                float bb = fs[0]; int bi2 = fi[0];
#pragma unroll
                for (int t = 1; t < 8; t++)
                    if (fs[t] < bb || (fs[t] == bb && fi[t] < bi2)) { bb = fs[t]; bi2 = fi[t]; }
                ridx[px] = bi2;
            }
            __syncthreads();
        }
    }

    if (tid < 128) out[1 + QELEMS + n0 + tid] = (float)ridx[tid];

    // gather quantized (exact f32), write BCHW, accumulate loss; last CTA finalizes
    {
        float* wsum = reinterpret_cast<float*>(sm + SM_WSUM);
        int px = tid & 127, ch = tid >> 7;
        int bi = ridx[px];
        const float4* erow = reinterpret_cast<const float4*>(emb + bi * CDIM);
        float* qout = out + 1 + (size_t)b * 262144 + rem + px;
        float lsum = 0.0f;
#pragma unroll
        for (int cc = 0; cc < 8; cc++) {
            int c = ch * 32 + cc * 4;
            float4 e4 = erow[c >> 2];
            float4 x4 = *reinterpret_cast<const float4*>(&sx[px * 68 + c]);
            float d0 = e4.x - x4.x, d1 = e4.y - x4.y;
            float d2 = e4.z - x4.z, d3 = e4.w - x4.w;
            lsum += d0 * d0 + d1 * d1 + d2 * d2 + d3 * d3;
            qout[(size_t)(c + 0) * 4096] = e4.x;
            qout[(size_t)(c + 1) * 4096] = e4.y;
            qout[(size_t)(c + 2) * 4096] = e4.z;
            qout[(size_t)(c + 3) * 4096] = e4.w;
        }
#pragma unroll
        for (int o = 16; o > 0; o >>= 1) lsum += __shfl_down_sync(0xffffffffu, lsum, o);
        if (l == 0) wsum[w] = lsum;
        __syncthreads();
        if (tid == 0) {
            float bsum = 0.0f;
#pragma unroll
            for (int ww = 0; ww < 8; ww++) bsum += wsum[ww];
            atomicAdd(&g_loss, bsum);
            __threadfence();
            int old = atomicAdd(&g_done, 1);
            if (old == NCTA - 1) {
                __threadfence();
                float total = atomicAdd(&g_loss, 0.0f);
                out[0] = 0.25f * total * (1.0f / (float)QELEMS);
            }
        }
    }
}

extern "C" void kernel_launch(void* const* d_in, const int* in_sizes, int n_in,
                              void* d_out, int out_size) {
    const float* x = (const float*)d_in[0];
    const float* emb = (const float*)d_in[1];
    if (n_in >= 2 && in_sizes[0] == KCODES * CDIM && in_sizes[1] == NPIX * CDIM) {
        const float* t = x; x = emb; emb = t;
    }
    float* out = (float*)d_out;
    (void)out_size;

    cudaFuncSetAttribute(vq_main, cudaFuncAttributeMaxDynamicSharedMemorySize, SM_TOTAL);

    vq_bsplit<<<8, 128>>>(emb);
    vq_main<<<NCTA, 256, SM_TOTAL>>>(x, emb, out);
}

// round 10
// speedup vs baseline: 1.6875x; 1.2809x over previous
#include <cuda_runtime.h>
#include <cuda_fp16.h>
#include <cstdint>

#define KCODES 1024
#define CDIM 64
#define NPIX 131072
#define QELEMS 8388608
#define TH2 0.002f      // gap threshold on score/2 (true err bound < 1e-4)
#define BIGF 3.4e38f
#define NCTA (NPIX / 128)

// g_B rows (136 halves, 272B): [-fp16(e) x64 | -(e - fp16(e)) x64 | pad x8]
__device__ __align__(16) __half g_B[KCODES * 136];
__device__ float g_enorm[KCODES];
__device__ float g_loss;
__device__ int g_done;

// ---- smem (bytes) ----
#define AROWB 272               // 136 halves/row (128 used), conflict-free ldmatrix
#define BROWB 272
#define BTILEB 17408            // 64 rows x 272B
#define SM_SA 0                 // 128 x 272 = 34816
#define SM_SB0 34816
#define SM_SB1 52224
#define SM_EN 69632             // float[1024]; overlaid by RB after main loop
#define SM_RB1 69632            // float [2][128]
#define SM_RB2 70656
#define SM_RI 71680
#define SM_MBAR 73728           // 2 x 8B mbarriers
#define SM_RIDX 73744           // int[128]
#define SM_FLIST 74256
#define SM_FCNT 74768
#define SM_WSUM 74772           // float[8]
#define SM_FS 74804             // float[8]
#define SM_FI 74836             // int[8]
#define SM_TOTAL 74880
// epilogue: sx f32 [128][68] @0 (34816) overlays sA (dead)

__device__ __forceinline__ uint32_t smem_u32(const void* p) {
    return (uint32_t)__cvta_generic_to_shared(p);
}
#define LDSM4(r0, r1, r2, r3, a)                                                  \
    asm volatile("ldmatrix.sync.aligned.m8n8.x4.shared.b16 {%0,%1,%2,%3}, [%4];"  \
                 : "=r"(r0), "=r"(r1), "=r"(r2), "=r"(r3) : "r"(a))
#define MMA16816(d, a, b)                                                         \
    asm volatile("mma.sync.aligned.m16n8k16.row.col.f32.f16.f16.f32 "             \
                 "{%0,%1,%2,%3}, {%4,%5,%6,%7}, {%8,%9}, {%0,%1,%2,%3};"          \
                 : "+f"((d)[0]), "+f"((d)[1]), "+f"((d)[2]), "+f"((d)[3])         \
                 : "r"((a)[0]), "r"((a)[1]), "r"((a)[2]), "r"((a)[3]),            \
                   "r"((b)[0]), "r"((b)[1]))

__device__ __forceinline__ void mbar_wait(uint32_t a, uint32_t ph) {
    uint32_t done;
    asm volatile("{\n\t.reg .pred p;\n\t"
                 "mbarrier.try_wait.parity.acquire.cta.shared::cta.b64 p, [%1], %2;\n\t"
                 "selp.b32 %0,1,0,p;\n\t}" : "=r"(done) : "r"(a), "r"(ph) : "memory");
    while (!done)
        asm volatile("{\n\t.reg .pred p;\n\t"
                     "mbarrier.try_wait.parity.acquire.cta.shared::cta.b64 p, [%1], %2, 0x989680;\n\t"
                     "selp.b32 %0,1,0,p;\n\t}" : "=r"(done) : "r"(a), "r"(ph) : "memory");
}
__device__ __forceinline__ void bulk_fetch(uint32_t dst, const void* src, uint32_t mbar) {
    asm volatile("mbarrier.arrive.expect_tx.shared.b64 _, [%0], %1;"
                 :: "r"(mbar), "r"((uint32_t)BTILEB) : "memory");
    asm volatile("cp.async.bulk.shared::cta.global.mbarrier::complete_tx::bytes "
                 "[%0], [%1], %2, [%3];"
                 :: "r"(dst), "l"(src), "r"((uint32_t)BTILEB), "r"(mbar) : "memory");
}

// ---------------- prep: B rows (-eh | -el | pad), enorm ----------------
__global__ void vq_bsplit(const float* __restrict__ emb) {
    int k = blockIdx.x * 128 + threadIdx.x;
    if (k == 0) { g_loss = 0.0f; g_done = 0; }
    if (k < KCODES) {
        float s = 0.0f;
        __half* br = g_B + k * 136;
#pragma unroll 8
        for (int c = 0; c < CDIM; c += 2) {
            float v0 = emb[k * CDIM + c], v1 = emb[k * CDIM + c + 1];
            s += v0 * v0 + v1 * v1;
            __half h0 = __float2half_rn(v0), h1 = __float2half_rn(v1);
            __half l0 = __float2half_rn(__half2float(h0) - v0);   // -(v - h)
            __half l1 = __float2half_rn(__half2float(h1) - v1);
            *reinterpret_cast<__half2*>(br + c) = __halves2half2(__hneg(h0), __hneg(h1));
            *reinterpret_cast<__half2*>(br + 64 + c) = __halves2half2(l0, l1);
        }
        g_enorm[k] = s;
#pragma unroll
        for (int c = 128; c < 136; c++) br[c] = __ushort_as_half((unsigned short)0);
    }
}

// ---------------- fused main ----------------
extern __shared__ char sm_raw[];

__global__ void __launch_bounds__(256, 3) vq_main(const float* __restrict__ x,
                                                  const float* __restrict__ emb,
                                                  float* __restrict__ out) {
    char* sm = sm_raw;
    __half* sA = reinterpret_cast<__half*>(sm + SM_SA);
    float* en2 = reinterpret_cast<float*>(sm + SM_EN);
    int* fcnt = reinterpret_cast<int*>(sm + SM_FCNT);

    const int tid = threadIdx.x, l = tid & 31, w = tid >> 5;
    const int wm = w & 3, wn = w >> 2;      // 4 m-blocks x 2 n-blocks
    const int n0 = blockIdx.x * 128;
    const int b = n0 >> 12, rem = n0 & 4095;
    const float* xb = x + (size_t)b * 262144 + rem;
    const uint32_t sBb = smem_u32(sm);
    const uint32_t mb0 = sBb + SM_MBAR, mb1 = sBb + SM_MBAR + 8;

    if (tid == 0) {
        asm volatile("mbarrier.init.shared.b64 [%0], 1;" :: "r"(mb0) : "memory");
        asm volatile("mbarrier.init.shared.b64 [%0], 1;" :: "r"(mb1) : "memory");
        *fcnt = 0;
    }
    __syncthreads();
    if (tid == 0) {   // prologue: tiles 0 and 1 in flight
        bulk_fetch(sBb + SM_SB0, (const char*)g_B, mb0);
        bulk_fetch(sBb + SM_SB1, (const char*)g_B + BTILEB, mb1);
    }

    for (int i = tid; i < KCODES; i += 256) en2[i] = 0.5f * g_enorm[i];
    // x -> sA: byte cols [0,128)=xh, [128,256)=xl
    for (int i = tid; i < 4096; i += 256) {
        int c2 = i >> 7, p = i & 127;
        float v0 = xb[(2 * c2) * 4096 + p], v1 = xb[(2 * c2 + 1) * 4096 + p];
        __half h0 = __float2half_rn(v0), h1 = __float2half_rn(v1);
        __half l0 = __float2half_rn(v0 - __half2float(h0));
        __half l1 = __float2half_rn(v1 - __half2float(h1));
        *reinterpret_cast<__half2*>(sA + p * 136 + 2 * c2) = __halves2half2(h0, h1);
        *reinterpret_cast<__half2*>(sA + p * 136 + 64 + 2 * c2) = __halves2half2(l0, l1);
    }
    __syncthreads();  // sA + en2 ready

    // lane-constant ldmatrix addresses
    const int lr = l & 7;
    const uint32_t aB = sBb + SM_SA +
        (uint32_t)(wm * 32 + lr + ((l >> 3) & 1) * 8) * AROWB + ((l >> 4) & 1) * 16;
    const uint32_t bO =
        (uint32_t)(wn * 32 + lr + ((l >> 4) & 1) * 8) * BROWB + ((l >> 3) & 1) * 16;

    float B1[4] = {BIGF, BIGF, BIGF, BIGF};
    float B2[4] = {BIGF, BIGF, BIGF, BIGF};
    int I1[4] = {0, 0, 0, 0};
    const int kwl = wn * 32 + 2 * (l & 3);
    const uint32_t bufOff[2] = {SM_SB0, SM_SB1};

    for (int nt = 0; nt < 16; nt++) {
        mbar_wait((nt & 1) ? mb1 : mb0, (nt >> 1) & 1);

        // acc init = enorm/2; MMA subtracts dot (B holds -e terms)
        float acc[2][4][4];
        {
            const int base = nt * 64 + kwl;
#pragma unroll
            for (int q = 0; q < 4; q++)
#pragma unroll
                for (int c1 = 0; c1 < 2; c1++) {
                    float e = en2[base + q * 8 + c1];
                    acc[0][q][c1] = e; acc[0][q][c1 + 2] = e;
                    acc[1][q][c1] = e; acc[1][q][c1 + 2] = e;
                }
        }

        const uint32_t bT = sBb + bufOff[nt & 1] + bO;
#pragma unroll
        for (int kq = 0; kq < 4; kq++) {
            const uint32_t cH = (uint32_t)kq * 32;        // xh / eh byte col
            const uint32_t cL = 128u + (uint32_t)kq * 32; // xl / el byte col
            uint32_t ah[2][4], al[2][4], bh[4][2], bl[4][2];
#pragma unroll
            for (int mt = 0; mt < 2; mt++) {
                LDSM4(ah[mt][0], ah[mt][1], ah[mt][2], ah[mt][3],
                      aB + (uint32_t)mt * (16 * AROWB) + cH);
                LDSM4(al[mt][0], al[mt][1], al[mt][2], al[mt][3],
                      aB + (uint32_t)mt * (16 * AROWB) + cL);
            }
#pragma unroll
            for (int q4 = 0; q4 < 2; q4++) {
                uint32_t r0, r1, r2, r3;
                LDSM4(r0, r1, r2, r3, bT + (uint32_t)q4 * (16 * BROWB) + cH);
                bh[q4 * 2][0] = r0; bh[q4 * 2][1] = r1;
                bh[q4 * 2 + 1][0] = r2; bh[q4 * 2 + 1][1] = r3;
                LDSM4(r0, r1, r2, r3, bT + (uint32_t)q4 * (16 * BROWB) + cL);
                bl[q4 * 2][0] = r0; bl[q4 * 2][1] = r1;
                bl[q4 * 2 + 1][0] = r2; bl[q4 * 2 + 1][1] = r3;
            }
#pragma unroll
            for (int mt = 0; mt < 2; mt++)
#pragma unroll
                for (int q = 0; q < 4; q++) {
                    MMA16816(acc[mt][q], ah[mt], bh[q]);  // xh . eh
                    MMA16816(acc[mt][q], al[mt], bh[q]);  // xl . eh
                    MMA16816(acc[mt][q], ah[mt], bl[q]);  // xh . el
                }
        }

        // fold (acc == score/2); codes ascend per slot -> strict < keeps lowest idx
        const int kb = nt * 64 + kwl;
#pragma unroll
        for (int mt = 0; mt < 2; mt++)
#pragma unroll
            for (int q = 0; q < 4; q++)
#pragma unroll
                for (int cc = 0; cc < 4; cc++) {
                    int code = kb + q * 8 + (cc & 1);
                    int s = mt * 2 + (cc >> 1);
                    float sc = acc[mt][q][cc];
                    if (sc < B1[s]) { B2[s] = B1[s]; B1[s] = sc; I1[s] = code; }
                    else B2[s] = fminf(B2[s], sc);
                }

        __syncthreads();  // all warps done reading buf[nt&1] this round
        if (nt < 14 && tid == 0)
            bulk_fetch(sBb + bufOff[nt & 1],
                       (const char*)g_B + (size_t)(nt + 2) * BTILEB,
                       (nt & 1) ? mb1 : mb0);
    }

    // quad reduce over lanes sharing pixel rows
#pragma unroll
    for (int off = 1; off <= 2; off <<= 1)
#pragma unroll
        for (int s = 0; s < 4; s++) {
            float ob1 = __shfl_down_sync(0xffffffffu, B1[s], off, 4);
            float ob2 = __shfl_down_sync(0xffffffffu, B2[s], off, 4);
            int oi = __shfl_down_sync(0xffffffffu, I1[s], off, 4);
            if (ob1 < B1[s] || (ob1 == B1[s] && oi < I1[s])) {
                B2[s] = fminf(ob2, B1[s]); B1[s] = ob1; I1[s] = oi;
            } else B2[s] = fminf(B2[s], ob1);
        }
    {   // RB arrays overlay en2 (dead after loop; last sync inside loop)
        float* rb1 = reinterpret_cast<float*>(sm + SM_RB1);
        float* rb2 = reinterpret_cast<float*>(sm + SM_RB2);
        int* ri = reinterpret_cast<int*>(sm + SM_RI);
        if ((l & 3) == 0)
#pragma unroll
            for (int s = 0; s < 4; s++) {
                int pr = wm * 32 + (s >> 1) * 16 + (s & 1) * 8 + (l >> 2);
                rb1[wn * 128 + pr] = B1[s];
                rb2[wn * 128 + pr] = B2[s];
                ri[wn * 128 + pr] = I1[s];
            }
    }
    __syncthreads();

    // reload exact fp32 x (overlays sA)
    float* sx = reinterpret_cast<float*>(sm + SM_SA);
    for (int i = tid; i < 8192; i += 256) {
        int c = i >> 7, p = i & 127;
        sx[p * 68 + c] = xb[c * 4096 + p];
    }

    int* ridx = reinterpret_cast<int*>(sm + SM_RIDX);
    int* flist = reinterpret_cast<int*>(sm + SM_FLIST);
    if (tid < 128) {
        float* rb1 = reinterpret_cast<float*>(sm + SM_RB1);
        float* rb2 = reinterpret_cast<float*>(sm + SM_RB2);
        int* ri = reinterpret_cast<int*>(sm + SM_RI);
        float a1 = rb1[tid], a2 = rb2[tid]; int ai = ri[tid];
        float c1 = rb1[128 + tid], c2 = rb2[128 + tid]; int ci = ri[128 + tid];
        float best, second; int bi;
        if (c1 < a1 || (c1 == a1 && ci < ai)) { best = c1; bi = ci; second = fminf(c2, a1); }
        else { best = a1; bi = ai; second = fminf(a2, c1); }
        ridx[tid] = bi;
        if (second - best < TH2) flist[atomicAdd(fcnt, 1)] = tid;
    }
    __syncthreads();

    // exact fp32 fixup for close calls (rare)
    {
        float* fs = reinterpret_cast<float*>(sm + SM_FS);
        int* fi = reinterpret_cast<int*>(sm + SM_FI);
        int nf = *fcnt;
        for (int f = 0; f < nf; f++) {
            int px = flist[f];
            float best = BIGF; int bidx = 0;
#pragma unroll
            for (int kk = 0; kk < 4; kk++) {
                int k = tid * 4 + kk;
                const float4* er = reinterpret_cast<const float4*>(emb + k * CDIM);
                float dot = 0.0f;
#pragma unroll
                for (int c4 = 0; c4 < 16; c4++) {
                    float4 e4 = er[c4];
                    float4 x4 = *reinterpret_cast<const float4*>(&sx[px * 68 + c4 * 4]);
                    dot += e4.x * x4.x + e4.y * x4.y + e4.z * x4.z + e4.w * x4.w;
                }
                float sc = fmaf(-2.0f, dot, __ldg(&g_enorm[k]));
                if (sc < best || (sc == best && k < bidx)) { best = sc; bidx = k; }
            }
#pragma unroll
            for (int off = 16; off > 0; off >>= 1) {
                float os = __shfl_down_sync(0xffffffffu, best, off);
                int oi = __shfl_down_sync(0xffffffffu, bidx, off);
                if (os < best || (os == best && oi < bidx)) { best = os; bidx = oi; }
            }
            if (l == 0) { fs[w] = best; fi[w] = bidx; }
            __syncthreads();
            if (tid == 0) {
                float bb = fs[0]; int bi2 = fi[0];
#pragma unroll
                for (int t = 1; t < 8; t++)
                    if (fs[t] < bb || (fs[t] == bb && fi[t] < bi2)) { bb = fs[t]; bi2 = fi[t]; }
                ridx[px] = bi2;
            }
            __syncthreads();
        }
    }

    if (tid < 128) out[1 + QELEMS + n0 + tid] = (float)ridx[tid];

    // gather quantized (exact f32), write BCHW, accumulate loss; last CTA finalizes
    {
        float* wsum = reinterpret_cast<float*>(sm + SM_WSUM);
        int px = tid & 127, ch = tid >> 7;
        int bi = ridx[px];
        const float4* erow = reinterpret_cast<const float4*>(emb + bi * CDIM);
        float* qout = out + 1 + (size_t)b * 262144 + rem + px;
        float lsum = 0.0f;
#pragma unroll
        for (int cc = 0; cc < 8; cc++) {
            int c = ch * 32 + cc * 4;
            float4 e4 = erow[c >> 2];
            float4 x4 = *reinterpret_cast<const float4*>(&sx[px * 68 + c]);
            float d0 = e4.x - x4.x, d1 = e4.y - x4.y;
            float d2 = e4.z - x4.z, d3 = e4.w - x4.w;
            lsum += d0 * d0 + d1 * d1 + d2 * d2 + d3 * d3;
            qout[(size_t)(c + 0) * 4096] = e4.x;
            qout[(size_t)(c + 1) * 4096] = e4.y;
            qout[(size_t)(c + 2) * 4096] = e4.z;
            qout[(size_t)(c + 3) * 4096] = e4.w;
        }
#pragma unroll
        for (int o = 16; o > 0; o >>= 1) lsum += __shfl_down_sync(0xffffffffu, lsum, o);
        if (l == 0) wsum[w] = lsum;
        __syncthreads();
        if (tid == 0) {
            float bsum = 0.0f;
#pragma unroll
            for (int ww = 0; ww < 8; ww++) bsum += wsum[ww];
            atomicAdd(&g_loss, bsum);
            __threadfence();
            int old = atomicAdd(&g_done, 1);
            if (old == NCTA - 1) {
                __threadfence();
                float total = atomicAdd(&g_loss, 0.0f);
                out[0] = 0.25f * total * (1.0f / (float)QELEMS);
            }
        }
    }
}

extern "C" void kernel_launch(void* const* d_in, const int* in_sizes, int n_in,
                              void* d_out, int out_size) {
    const float* x = (const float*)d_in[0];
    const float* emb = (const float*)d_in[1];
    if (n_in >= 2 && in_sizes[0] == KCODES * CDIM && in_sizes[1] == NPIX * CDIM) {
        const float* t = x; x = emb; emb = t;
    }
    float* out = (float*)d_out;
    (void)out_size;

    cudaFuncSetAttribute(vq_main, cudaFuncAttributeMaxDynamicSharedMemorySize, SM_TOTAL);

    vq_bsplit<<<8, 128>>>(emb);
    vq_main<<<NCTA, 256, SM_TOTAL>>>(x, emb, out);
}